// round 1
// baseline (speedup 1.0000x reference)
#include <cuda_runtime.h>
#include <cstddef>

#define N_LANE  20000
#define P_LANE  20
#define N_AGENT 4000
#define T_AGENT 20
#define F_DIM   8
#define H_DIM   128
#define E_LL    640000
#define E_AA    128000
#define E_LA    200000

// ---------------- scratch (device globals; no allocation allowed) -----------
__device__ float g_lane_enc [N_LANE  * H_DIM];
__device__ float g_agent_enc[N_AGENT * H_DIM];
__device__ float g_lane_agg [N_LANE  * H_DIM];
__device__ float g_agent_agg[N_AGENT * H_DIM];
__device__ float g_deg_l[N_LANE];
__device__ float g_deg_a[N_AGENT];

// ---------------- zero kernels ---------------------------------------------
__global__ void zero_all_kernel() {
    int i = blockIdx.x * blockDim.x + threadIdx.x;
    int stride = gridDim.x * blockDim.x;
    for (int k = i; k < N_LANE * H_DIM; k += stride) g_lane_agg[k] = 0.f;
    for (int k = i; k < N_AGENT * H_DIM; k += stride) g_agent_agg[k] = 0.f;
    for (int k = i; k < N_LANE; k += stride) g_deg_l[k] = 0.f;
    for (int k = i; k < N_AGENT; k += stride) g_deg_a[k] = 0.f;
}
__global__ void zero_agent_kernel() {
    int i = blockIdx.x * blockDim.x + threadIdx.x;
    int stride = gridDim.x * blockDim.x;
    for (int k = i; k < N_AGENT * H_DIM; k += stride) g_agent_agg[k] = 0.f;
    for (int k = i; k < N_AGENT; k += stride) g_deg_a[k] = 0.f;
}

// ---------------- encoder ---------------------------------------------------
// smem layout (floats):
//  w1s[8*128] w2s[128*128] w3s[128*128] b1s[128] b2s[128] b3s[128]
//  h1T[128*20] (k-major, t contiguous)  ms[128]  xs[160]
#define ENC_SMEM_FLOATS (8*H_DIM + H_DIM*H_DIM + H_DIM*H_DIM + 3*H_DIM + H_DIM*P_LANE + H_DIM + P_LANE*F_DIM)
#define ENC_SMEM_BYTES  (ENC_SMEM_FLOATS * 4)

__global__ void __launch_bounds__(128, 1)
encode_kernel(const float* __restrict__ x_in,
              const float* __restrict__ w1, const float* __restrict__ b1,
              const float* __restrict__ w2, const float* __restrict__ b2,
              const float* __restrict__ w3, const float* __restrict__ b3,
              float* __restrict__ out, int n_nodes, int nodes_per_block)
{
    extern __shared__ float smem[];
    float* w1s = smem;
    float* w2s = w1s + 8 * H_DIM;
    float* w3s = w2s + H_DIM * H_DIM;
    float* b1s = w3s + H_DIM * H_DIM;
    float* b2s = b1s + H_DIM;
    float* b3s = b2s + H_DIM;
    float* h1T = b3s + H_DIM;             // [k][t], row stride 20 floats (80B)
    float* ms  = h1T + H_DIM * P_LANE;
    float* xs  = ms + H_DIM;              // [t][f], 160 floats

    const int tid = threadIdx.x;          // 128 threads
    for (int i = tid; i < 8 * H_DIM; i += 128) w1s[i] = w1[i];
    for (int i = tid; i < H_DIM * H_DIM; i += 128) w2s[i] = w2[i];
    for (int i = tid; i < H_DIM * H_DIM; i += 128) w3s[i] = w3[i];
    b1s[tid] = b1[tid];
    b2s[tid] = b2[tid];
    b3s[tid] = b3[tid];
    __syncthreads();

    // hoisted per-thread weights
    float wa[F_DIM];
#pragma unroll
    for (int f = 0; f < F_DIM; f++) wa[f] = w1s[f * H_DIM + tid];
    const float b1v = b1s[tid];
    const float b2v = b2s[tid];
    const float b3v = b3s[tid];

    const int node0 = blockIdx.x * nodes_per_block;
    int node1 = node0 + nodes_per_block;
    if (node1 > n_nodes) node1 = n_nodes;

    for (int node = node0; node < node1; node++) {
        // load x (20x8)
        const float* xg = x_in + (size_t)node * (P_LANE * F_DIM);
        for (int i = tid; i < P_LANE * F_DIM; i += 128) xs[i] = xg[i];
        __syncthreads();

        const float rx = xs[(P_LANE - 1) * F_DIM + 0];
        const float ry = xs[(P_LANE - 1) * F_DIM + 1];

        // stage B: h1[t][tid] -> h1T[tid][t]
#pragma unroll
        for (int t = 0; t < P_LANE; t++) {
            const float* xr = xs + t * F_DIM;
            float s = b1v;
            s = fmaf(xr[0] - rx, wa[0], s);
            s = fmaf(xr[1] - ry, wa[1], s);
#pragma unroll
            for (int f = 2; f < F_DIM; f++) s = fmaf(xr[f], wa[f], s);
            h1T[tid * P_LANE + t] = fmaxf(s, 0.f);
        }
        __syncthreads();

        // stage C: h2[t][tid] = b2 + sum_k h1[t][k]*w2[k][tid]; 20 indep chains
        float acc[P_LANE];
#pragma unroll
        for (int t = 0; t < P_LANE; t++) acc[t] = b2v;
        const float4* h14 = (const float4*)h1T;
#pragma unroll 4
        for (int k = 0; k < H_DIM; k++) {
            const float wv = w2s[k * H_DIM + tid];
            const float4 a0 = h14[k * 5 + 0];
            const float4 a1 = h14[k * 5 + 1];
            const float4 a2 = h14[k * 5 + 2];
            const float4 a3 = h14[k * 5 + 3];
            const float4 a4 = h14[k * 5 + 4];
            acc[0]  = fmaf(a0.x, wv, acc[0]);
            acc[1]  = fmaf(a0.y, wv, acc[1]);
            acc[2]  = fmaf(a0.z, wv, acc[2]);
            acc[3]  = fmaf(a0.w, wv, acc[3]);
            acc[4]  = fmaf(a1.x, wv, acc[4]);
            acc[5]  = fmaf(a1.y, wv, acc[5]);
            acc[6]  = fmaf(a1.z, wv, acc[6]);
            acc[7]  = fmaf(a1.w, wv, acc[7]);
            acc[8]  = fmaf(a2.x, wv, acc[8]);
            acc[9]  = fmaf(a2.y, wv, acc[9]);
            acc[10] = fmaf(a2.z, wv, acc[10]);
            acc[11] = fmaf(a2.w, wv, acc[11]);
            acc[12] = fmaf(a3.x, wv, acc[12]);
            acc[13] = fmaf(a3.y, wv, acc[13]);
            acc[14] = fmaf(a3.z, wv, acc[14]);
            acc[15] = fmaf(a3.w, wv, acc[15]);
            acc[16] = fmaf(a4.x, wv, acc[16]);
            acc[17] = fmaf(a4.y, wv, acc[17]);
            acc[18] = fmaf(a4.z, wv, acc[18]);
            acc[19] = fmaf(a4.w, wv, acc[19]);
        }
        float m = acc[0];
#pragma unroll
        for (int t = 1; t < P_LANE; t++) m = fmaxf(m, acc[t]);
        m = fmaxf(m, 0.f);     // max(relu(.)) == relu(max(.))
        ms[tid] = m;
        __syncthreads();

        // stage D: out = relu(ms @ w3 + b3)
        float s0 = 0.f, s1 = 0.f, s2 = 0.f, s3 = 0.f;
        const float4* ms4 = (const float4*)ms;
#pragma unroll
        for (int k = 0; k < H_DIM; k += 4) {
            const float4 mv = ms4[k >> 2];
            s0 = fmaf(mv.x, w3s[(k + 0) * H_DIM + tid], s0);
            s1 = fmaf(mv.y, w3s[(k + 1) * H_DIM + tid], s1);
            s2 = fmaf(mv.z, w3s[(k + 2) * H_DIM + tid], s2);
            s3 = fmaf(mv.w, w3s[(k + 3) * H_DIM + tid], s3);
        }
        out[(size_t)node * H_DIM + tid] = fmaxf((s0 + s1) + (s2 + s3) + b3v, 0.f);
        __syncthreads();   // protect xs/h1T/ms for next node
    }
}

// ---------------- edge scatter (segment_sum via vector RED) -----------------
__global__ void scatter_kernel(const int* __restrict__ src_idx,
                               const int* __restrict__ dst_idx, int n_edges,
                               const float* __restrict__ feat,
                               float* __restrict__ agg, float* __restrict__ deg)
{
    const int warp = (blockIdx.x * blockDim.x + threadIdx.x) >> 5;
    const int lane = threadIdx.x & 31;
    if (warp >= n_edges) return;
    const int s = src_idx[warp];
    const int d = dst_idx[warp];
    const float4 v = ((const float4*)(feat + (size_t)s * H_DIM))[lane];
    float4* a = ((float4*)(agg + (size_t)d * H_DIM)) + lane;
    asm volatile("red.global.add.v4.f32 [%0], {%1,%2,%3,%4};"
                 :: "l"(a), "f"(v.x), "f"(v.y), "f"(v.z), "f"(v.w) : "memory");
    if (lane == 0) atomicAdd(deg + d, 1.0f);
}

// ---------------- edge GNN node MLP -----------------------------------------
// smem: w1s[256*128] w2s[128*128] b1s[128] b2s[128] ins[256] hs[128]
#define GNN_SMEM_FLOATS (2*H_DIM*H_DIM + H_DIM*H_DIM + 2*H_DIM + 2*H_DIM + H_DIM)
#define GNN_SMEM_BYTES  (GNN_SMEM_FLOATS * 4)

__global__ void __launch_bounds__(128, 1)
gnn_kernel(const float* __restrict__ node_in,
           const float* __restrict__ agg, const float* __restrict__ deg,
           const float* __restrict__ w1, const float* __restrict__ b1,
           const float* __restrict__ w2, const float* __restrict__ b2,
           float* __restrict__ out, int n_nodes, int nodes_per_block)
{
    extern __shared__ float smem[];
    float* w1s = smem;                         // 256*128
    float* w2s = w1s + 2 * H_DIM * H_DIM;      // 128*128
    float* b1s = w2s + H_DIM * H_DIM;
    float* b2s = b1s + H_DIM;
    float* ins = b2s + H_DIM;                  // 256
    float* hs  = ins + 2 * H_DIM;              // 128

    const int tid = threadIdx.x;
    for (int i = tid; i < 2 * H_DIM * H_DIM; i += 128) w1s[i] = w1[i];
    for (int i = tid; i < H_DIM * H_DIM; i += 128) w2s[i] = w2[i];
    b1s[tid] = b1[tid];
    b2s[tid] = b2[tid];
    __syncthreads();

    const float b1v = b1s[tid];
    const float b2v = b2s[tid];

    const int node0 = blockIdx.x * nodes_per_block;
    int node1 = node0 + nodes_per_block;
    if (node1 > n_nodes) node1 = n_nodes;

    for (int node = node0; node < node1; node++) {
        const float nv = node_in[(size_t)node * H_DIM + tid];
        const float invd = 1.0f / fmaxf(deg[node], 1.0f);
        ins[tid] = nv;
        ins[H_DIM + tid] = agg[(size_t)node * H_DIM + tid] * invd;
        __syncthreads();

        // h = relu([node,agg] @ w1 + b1), K = 256, 4 indep chains
        float s0 = 0.f, s1 = 0.f, s2 = 0.f, s3 = 0.f;
        const float4* in4 = (const float4*)ins;
#pragma unroll 8
        for (int k = 0; k < 2 * H_DIM; k += 4) {
            const float4 iv = in4[k >> 2];
            s0 = fmaf(iv.x, w1s[(k + 0) * H_DIM + tid], s0);
            s1 = fmaf(iv.y, w1s[(k + 1) * H_DIM + tid], s1);
            s2 = fmaf(iv.z, w1s[(k + 2) * H_DIM + tid], s2);
            s3 = fmaf(iv.w, w1s[(k + 3) * H_DIM + tid], s3);
        }
        hs[tid] = fmaxf((s0 + s1) + (s2 + s3) + b1v, 0.f);
        __syncthreads();

        // o = relu(h @ w2 + b2); out = node + o
        s0 = s1 = s2 = s3 = 0.f;
        const float4* h4 = (const float4*)hs;
#pragma unroll 8
        for (int k = 0; k < H_DIM; k += 4) {
            const float4 hv = h4[k >> 2];
            s0 = fmaf(hv.x, w2s[(k + 0) * H_DIM + tid], s0);
            s1 = fmaf(hv.y, w2s[(k + 1) * H_DIM + tid], s1);
            s2 = fmaf(hv.z, w2s[(k + 2) * H_DIM + tid], s2);
            s3 = fmaf(hv.w, w2s[(k + 3) * H_DIM + tid], s3);
        }
        const float o = fmaxf((s0 + s1) + (s2 + s3) + b2v, 0.f);
        out[(size_t)node * H_DIM + tid] = nv + o;
        __syncthreads();   // protect ins/hs for next node
    }
}

// ---------------- launch -----------------------------------------------------
extern "C" void kernel_launch(void* const* d_in, const int* in_sizes, int n_in,
                              void* d_out, int out_size)
{
    const float* lane_points   = (const float*)d_in[0];
    const float* agent_history = (const float*)d_in[1];
    const int* e_ll = (const int*)d_in[2];
    const int* e_aa = (const int*)d_in[3];
    const int* e_la = (const int*)d_in[4];
    const float* lw1 = (const float*)d_in[5];
    const float* lb1 = (const float*)d_in[6];
    const float* lw2 = (const float*)d_in[7];
    const float* lb2 = (const float*)d_in[8];
    const float* lw3 = (const float*)d_in[9];
    const float* lb3 = (const float*)d_in[10];
    const float* aw1 = (const float*)d_in[11];
    const float* ab1 = (const float*)d_in[12];
    const float* aw2 = (const float*)d_in[13];
    const float* ab2 = (const float*)d_in[14];
    const float* aw3 = (const float*)d_in[15];
    const float* ab3 = (const float*)d_in[16];
    const float* ll_w1 = (const float*)d_in[17];
    const float* ll_b1 = (const float*)d_in[18];
    const float* ll_w2 = (const float*)d_in[19];
    const float* ll_b2 = (const float*)d_in[20];
    const float* aa_w1 = (const float*)d_in[21];
    const float* aa_b1 = (const float*)d_in[22];
    const float* aa_w2 = (const float*)d_in[23];
    const float* aa_b2 = (const float*)d_in[24];
    const float* la_w1 = (const float*)d_in[25];
    const float* la_b1 = (const float*)d_in[26];
    const float* la_w2 = (const float*)d_in[27];
    const float* la_b2 = (const float*)d_in[28];

    float* out = (float*)d_out;
    float* lane_out  = out;
    float* agent_out = out + (size_t)N_LANE * H_DIM;

    float *p_lane_enc, *p_agent_enc, *p_lane_agg, *p_agent_agg, *p_deg_l, *p_deg_a;
    cudaGetSymbolAddress((void**)&p_lane_enc,  g_lane_enc);
    cudaGetSymbolAddress((void**)&p_agent_enc, g_agent_enc);
    cudaGetSymbolAddress((void**)&p_lane_agg,  g_lane_agg);
    cudaGetSymbolAddress((void**)&p_agent_agg, g_agent_agg);
    cudaGetSymbolAddress((void**)&p_deg_l,     g_deg_l);
    cudaGetSymbolAddress((void**)&p_deg_a,     g_deg_a);

    cudaFuncSetAttribute(encode_kernel, cudaFuncAttributeMaxDynamicSharedMemorySize, ENC_SMEM_BYTES);
    cudaFuncSetAttribute(gnn_kernel,    cudaFuncAttributeMaxDynamicSharedMemorySize, GNN_SMEM_BYTES);

    zero_all_kernel<<<2048, 256>>>();

    // encoders
    encode_kernel<<<(N_LANE + 19) / 20, 128, ENC_SMEM_BYTES>>>(
        lane_points, lw1, lb1, lw2, lb2, lw3, lb3, p_lane_enc, N_LANE, 20);
    encode_kernel<<<(N_AGENT + 19) / 20, 128, ENC_SMEM_BYTES>>>(
        agent_history, aw1, ab1, aw2, ab2, aw3, ab3, p_agent_enc, N_AGENT, 20);

    // lane-lane GNN
    scatter_kernel<<<(E_LL + 7) / 8, 256>>>(e_ll, e_ll + E_LL, E_LL,
                                            p_lane_enc, p_lane_agg, p_deg_l);
    gnn_kernel<<<(N_LANE + 67) / 68, 128, GNN_SMEM_BYTES>>>(
        p_lane_enc, p_lane_agg, p_deg_l, ll_w1, ll_b1, ll_w2, ll_b2,
        lane_out, N_LANE, 68);

    // agent-agent GNN
    scatter_kernel<<<(E_AA + 7) / 8, 256>>>(e_aa, e_aa + E_AA, E_AA,
                                            p_agent_enc, p_agent_agg, p_deg_a);
    gnn_kernel<<<(N_AGENT + 26) / 27, 128, GNN_SMEM_BYTES>>>(
        p_agent_enc, p_agent_agg, p_deg_a, aa_w1, aa_b1, aa_w2, aa_b2,
        agent_out, N_AGENT, 27);

    // lane-agent GNN (source = updated lane, node = updated agent, in-place)
    zero_agent_kernel<<<1024, 256>>>();
    scatter_kernel<<<(E_LA + 7) / 8, 256>>>(e_la, e_la + E_LA, E_LA,
                                            lane_out, p_agent_agg, p_deg_a);
    gnn_kernel<<<(N_AGENT + 26) / 27, 128, GNN_SMEM_BYTES>>>(
        agent_out, p_agent_agg, p_deg_a, la_w1, la_b1, la_w2, la_b2,
        agent_out, N_AGENT, 27);
}

// round 2
// speedup vs baseline: 1.3563x; 1.3563x over previous
#include <cuda_runtime.h>
#include <cstddef>

#define N_LANE  20000
#define P_LANE  20
#define N_AGENT 4000
#define T_AGENT 20
#define F_DIM   8
#define H_DIM   128
#define E_LL    640000
#define E_AA    128000
#define E_LA    200000

// ---------------- scratch (device globals; no allocation allowed) -----------
__device__ float g_lane_enc [N_LANE  * H_DIM];
__device__ float g_agent_enc[N_AGENT * H_DIM];
__device__ float g_lane_agg [N_LANE  * H_DIM];
__device__ float g_agent_agg[N_AGENT * H_DIM];
__device__ float g_deg_l[N_LANE];
__device__ float g_deg_a[N_AGENT];

// ---------------- packed f32x2 helpers --------------------------------------
__device__ __forceinline__ void ffma2(unsigned long long& d,
                                      unsigned long long a,
                                      unsigned long long b) {
    asm("fma.rn.f32x2 %0, %1, %2, %0;" : "+l"(d) : "l"(a), "l"(b));
}
__device__ __forceinline__ unsigned long long pack_dup(float x) {
    unsigned long long r;
    unsigned u = __float_as_uint(x);
    asm("mov.b64 %0, {%1, %2};" : "=l"(r) : "r"(u), "r"(u));
    return r;
}
__device__ __forceinline__ float2 unpack2(unsigned long long v) {
    unsigned lo, hi;
    asm("mov.b64 {%0, %1}, %2;" : "=r"(lo), "=r"(hi) : "l"(v));
    return make_float2(__uint_as_float(lo), __uint_as_float(hi));
}

// ---------------- zero kernels ---------------------------------------------
__global__ void zero_all_kernel() {
    int i = blockIdx.x * blockDim.x + threadIdx.x;
    int stride = gridDim.x * blockDim.x;
    for (int k = i; k < N_LANE * H_DIM; k += stride) g_lane_agg[k] = 0.f;
    for (int k = i; k < N_AGENT * H_DIM; k += stride) g_agent_agg[k] = 0.f;
    for (int k = i; k < N_LANE; k += stride) g_deg_l[k] = 0.f;
    for (int k = i; k < N_AGENT; k += stride) g_deg_a[k] = 0.f;
}
__global__ void zero_agent_kernel() {
    int i = blockIdx.x * blockDim.x + threadIdx.x;
    int stride = gridDim.x * blockDim.x;
    for (int k = i; k < N_AGENT * H_DIM; k += stride) g_agent_agg[k] = 0.f;
    for (int k = i; k < N_AGENT; k += stride) g_deg_a[k] = 0.f;
}

// ---------------- encoder ---------------------------------------------------
// 256 threads, 2 node-slots. smem (floats):
//   w1s[8*128] w2s[128*128] w3s[128*128] b1s/b2s/b3s[128]
//   h1T[2][128*20]  ms[2][128]  xs[2][160]
#define ENC_SMEM_FLOATS (8*H_DIM + 2*H_DIM*H_DIM + 3*H_DIM + 2*H_DIM*P_LANE + 2*H_DIM + 2*P_LANE*F_DIM)
#define ENC_SMEM_BYTES  (ENC_SMEM_FLOATS * 4)

__global__ void __launch_bounds__(256, 1)
encode_kernel(const float* __restrict__ x_in,
              const float* __restrict__ w1, const float* __restrict__ b1,
              const float* __restrict__ w2, const float* __restrict__ b2,
              const float* __restrict__ w3, const float* __restrict__ b3,
              float* __restrict__ out, int n_nodes, int nodes_per_block)
{
    extern __shared__ float smem[];
    float* w1s  = smem;                       // 1024
    float* w2s  = w1s + 8 * H_DIM;            // 16384
    float* w3s  = w2s + H_DIM * H_DIM;        // 16384
    float* b1s  = w3s + H_DIM * H_DIM;        // 128
    float* b2s  = b1s + H_DIM;
    float* b3s  = b2s + H_DIM;
    float* h1T0 = b3s + H_DIM;                // 2 * 2560
    float* ms0  = h1T0 + 2 * H_DIM * P_LANE;  // 2 * 128
    float* xs0  = ms0 + 2 * H_DIM;            // 2 * 160

    const int tid  = threadIdx.x;             // 0..255
    const int slot = tid >> 7;
    const int t0   = tid & 127;
    float* h1T = h1T0 + slot * (H_DIM * P_LANE);
    float* ms  = ms0  + slot * H_DIM;
    float* xs  = xs0  + slot * (P_LANE * F_DIM);

    for (int i = tid; i < 8 * H_DIM; i += 256) w1s[i] = w1[i];
    for (int i = tid; i < H_DIM * H_DIM; i += 256) w2s[i] = w2[i];
    for (int i = tid; i < H_DIM * H_DIM; i += 256) w3s[i] = w3[i];
    if (tid < H_DIM) { b1s[tid] = b1[tid]; b2s[tid] = b2[tid]; b3s[tid] = b3[tid]; }
    __syncthreads();

    float wa[F_DIM];
#pragma unroll
    for (int f = 0; f < F_DIM; f++) wa[f] = w1s[f * H_DIM + t0];
    const float b1v = b1s[t0];
    const float b2v = b2s[t0];
    const float b3v = b3s[t0];

    const int node0 = blockIdx.x * nodes_per_block;
    int node1 = node0 + nodes_per_block;
    if (node1 > n_nodes) node1 = n_nodes;

    for (int nb = node0; nb < node1; nb += 2) {
        const int node  = nb + slot;
        const bool valid = node < node1;
        const int nclamp = valid ? node : (node1 - 1);

        // load x (20x8) for this slot's node
        const float* xg = x_in + (size_t)nclamp * (P_LANE * F_DIM);
        for (int i = t0; i < P_LANE * F_DIM; i += 128) xs[i] = xg[i];
        __syncthreads();

        const float rx = xs[(P_LANE - 1) * F_DIM + 0];
        const float ry = xs[(P_LANE - 1) * F_DIM + 1];

        // stage B: h1[t][t0] -> h1T[t0][t]
#pragma unroll
        for (int t = 0; t < P_LANE; t++) {
            const float* xr = xs + t * F_DIM;
            float s = b1v;
            s = fmaf(xr[0] - rx, wa[0], s);
            s = fmaf(xr[1] - ry, wa[1], s);
#pragma unroll
            for (int f = 2; f < F_DIM; f++) s = fmaf(xr[f], wa[f], s);
            h1T[t0 * P_LANE + t] = fmaxf(s, 0.f);
        }
        __syncthreads();

        // stage C: packed f32x2, 10 chains over t-pairs
        unsigned long long acc2[10];
        {
            const unsigned long long bp = pack_dup(b2v);
#pragma unroll
            for (int j = 0; j < 10; j++) acc2[j] = bp;
        }
#pragma unroll 2
        for (int k = 0; k < H_DIM; k++) {
            const unsigned long long wp = pack_dup(w2s[k * H_DIM + t0]);
            const ulonglong2* hp = ((const ulonglong2*)h1T) + k * 5;
            const ulonglong2 q0 = hp[0];
            const ulonglong2 q1 = hp[1];
            const ulonglong2 q2 = hp[2];
            const ulonglong2 q3 = hp[3];
            const ulonglong2 q4 = hp[4];
            ffma2(acc2[0], q0.x, wp);
            ffma2(acc2[1], q0.y, wp);
            ffma2(acc2[2], q1.x, wp);
            ffma2(acc2[3], q1.y, wp);
            ffma2(acc2[4], q2.x, wp);
            ffma2(acc2[5], q2.y, wp);
            ffma2(acc2[6], q3.x, wp);
            ffma2(acc2[7], q3.y, wp);
            ffma2(acc2[8], q4.x, wp);
            ffma2(acc2[9], q4.y, wp);
        }
        float m = 0.f;   // max(relu(.)) == relu(max(.)), relu lower-bounds at 0
#pragma unroll
        for (int j = 0; j < 10; j++) {
            const float2 v = unpack2(acc2[j]);
            m = fmaxf(m, fmaxf(v.x, v.y));
        }
        ms[t0] = m;
        __syncthreads();

        // stage D: out = relu(ms @ w3 + b3)
        float s0 = 0.f, s1 = 0.f, s2 = 0.f, s3 = 0.f;
        const float4* ms4 = (const float4*)ms;
#pragma unroll
        for (int k = 0; k < H_DIM; k += 4) {
            const float4 mv = ms4[k >> 2];
            s0 = fmaf(mv.x, w3s[(k + 0) * H_DIM + t0], s0);
            s1 = fmaf(mv.y, w3s[(k + 1) * H_DIM + t0], s1);
            s2 = fmaf(mv.z, w3s[(k + 2) * H_DIM + t0], s2);
            s3 = fmaf(mv.w, w3s[(k + 3) * H_DIM + t0], s3);
        }
        if (valid)
            out[(size_t)node * H_DIM + t0] = fmaxf((s0 + s1) + (s2 + s3) + b3v, 0.f);
        __syncthreads();   // protect xs/h1T/ms reuse
    }
}

// ---------------- edge scatter (segment_sum via vector RED) -----------------
__global__ void scatter_kernel(const int* __restrict__ src_idx,
                               const int* __restrict__ dst_idx, int n_edges,
                               const float* __restrict__ feat,
                               float* __restrict__ agg, float* __restrict__ deg)
{
    const int warp = (blockIdx.x * blockDim.x + threadIdx.x) >> 5;
    const int lane = threadIdx.x & 31;
    if (warp >= n_edges) return;
    const int s = src_idx[warp];
    const int d = dst_idx[warp];
    const float4 v = ((const float4*)(feat + (size_t)s * H_DIM))[lane];
    float4* a = ((float4*)(agg + (size_t)d * H_DIM)) + lane;
    asm volatile("red.global.add.v4.f32 [%0], {%1,%2,%3,%4};"
                 :: "l"(a), "f"(v.x), "f"(v.y), "f"(v.z), "f"(v.w) : "memory");
    if (lane == 0) atomicAdd(deg + d, 1.0f);
}

// ---------------- edge GNN node MLP: 8-node register-blocked GEMM -----------
// smem: w1s[256*128] w2s[128*128] b1s[128] b2s[128] insT[256*8] hT[128*8]
#define GNN_NB 8
#define GNN_SMEM_FLOATS (2*H_DIM*H_DIM + H_DIM*H_DIM + 2*H_DIM + 2*H_DIM*GNN_NB + H_DIM*GNN_NB)
#define GNN_SMEM_BYTES  (GNN_SMEM_FLOATS * 4)

__global__ void __launch_bounds__(128, 1)
gnn_kernel(const float* __restrict__ node_in,
           const float* __restrict__ agg, const float* __restrict__ deg,
           const float* __restrict__ w1, const float* __restrict__ b1,
           const float* __restrict__ w2, const float* __restrict__ b2,
           float* __restrict__ out, int n_nodes, int nodes_per_block)
{
    extern __shared__ float smem[];
    float* w1s  = smem;                          // 256*128
    float* w2s  = w1s + 2 * H_DIM * H_DIM;       // 128*128
    float* b1s  = w2s + H_DIM * H_DIM;           // 128
    float* b2s  = b1s + H_DIM;                   // 128
    float* insT = b2s + H_DIM;                   // [256][8]
    float* hT   = insT + 2 * H_DIM * GNN_NB;     // [128][8]

    const int tid = threadIdx.x;
    for (int i = tid; i < 2 * H_DIM * H_DIM; i += 128) w1s[i] = w1[i];
    for (int i = tid; i < H_DIM * H_DIM; i += 128) w2s[i] = w2[i];
    if (tid < H_DIM) { b1s[tid] = b1[tid]; b2s[tid] = b2[tid]; }
    __syncthreads();

    const float b1v = b1s[tid];
    const float b2v = b2s[tid];

    const int node0 = blockIdx.x * nodes_per_block;
    int node1 = node0 + nodes_per_block;
    if (node1 > n_nodes) node1 = n_nodes;

    const int jld = tid >> 4;      // node slot this thread loads (0..7)
    const int lld = tid & 15;      // 16 threads per node

    for (int g = node0; g < node1; g += GNN_NB) {
        // ---- load 8 nodes' [node, agg/deg] transposed into insT[k][j] ----
        {
            int nd = g + jld;
            if (nd >= n_nodes) nd = n_nodes - 1;
            const float invd = 1.0f / fmaxf(deg[nd], 1.0f);
            const float* np = node_in + (size_t)nd * H_DIM;
            const float* ap = agg + (size_t)nd * H_DIM;
#pragma unroll
            for (int r = 0; r < 8; r++) {
                const int k = lld + 16 * r;
                insT[k * GNN_NB + jld] = np[k];
                insT[(H_DIM + k) * GNN_NB + jld] = ap[k] * invd;
            }
        }
        __syncthreads();

        // ---- layer 1: h[tid][j] = relu(b1 + sum_k insT[k][j]*w1[k][tid]) ----
        unsigned long long acc[4];
        {
            const unsigned long long bp = pack_dup(b1v);
#pragma unroll
            for (int j = 0; j < 4; j++) acc[j] = bp;
        }
#pragma unroll 4
        for (int k = 0; k < 2 * H_DIM; k++) {
            const unsigned long long wp = pack_dup(w1s[k * H_DIM + tid]);
            const ulonglong2* ip = ((const ulonglong2*)insT) + k * 2;
            const ulonglong2 a = ip[0];
            const ulonglong2 b = ip[1];
            ffma2(acc[0], a.x, wp);
            ffma2(acc[1], a.y, wp);
            ffma2(acc[2], b.x, wp);
            ffma2(acc[3], b.y, wp);
        }
        {
            const float2 v0 = unpack2(acc[0]);
            const float2 v1 = unpack2(acc[1]);
            const float2 v2 = unpack2(acc[2]);
            const float2 v3 = unpack2(acc[3]);
            float4* hp = (float4*)(hT + tid * GNN_NB);
            hp[0] = make_float4(fmaxf(v0.x, 0.f), fmaxf(v0.y, 0.f),
                                fmaxf(v1.x, 0.f), fmaxf(v1.y, 0.f));
            hp[1] = make_float4(fmaxf(v2.x, 0.f), fmaxf(v2.y, 0.f),
                                fmaxf(v3.x, 0.f), fmaxf(v3.y, 0.f));
        }
        __syncthreads();

        // ---- layer 2: o[tid][j] = relu(b2 + sum_k hT[k][j]*w2[k][tid]) ----
        {
            const unsigned long long bp = pack_dup(b2v);
#pragma unroll
            for (int j = 0; j < 4; j++) acc[j] = bp;
        }
#pragma unroll 4
        for (int k = 0; k < H_DIM; k++) {
            const unsigned long long wp = pack_dup(w2s[k * H_DIM + tid]);
            const ulonglong2* hp = ((const ulonglong2*)hT) + k * 2;
            const ulonglong2 a = hp[0];
            const ulonglong2 b = hp[1];
            ffma2(acc[0], a.x, wp);
            ffma2(acc[1], a.y, wp);
            ffma2(acc[2], b.x, wp);
            ffma2(acc[3], b.y, wp);
        }

        // ---- residual + store: out[nd][tid] = insT[tid][j] + relu(o) ----
        float o[GNN_NB];
        {
            const float2 v0 = unpack2(acc[0]);
            const float2 v1 = unpack2(acc[1]);
            const float2 v2 = unpack2(acc[2]);
            const float2 v3 = unpack2(acc[3]);
            o[0] = fmaxf(v0.x, 0.f); o[1] = fmaxf(v0.y, 0.f);
            o[2] = fmaxf(v1.x, 0.f); o[3] = fmaxf(v1.y, 0.f);
            o[4] = fmaxf(v2.x, 0.f); o[5] = fmaxf(v2.y, 0.f);
            o[6] = fmaxf(v3.x, 0.f); o[7] = fmaxf(v3.y, 0.f);
        }
#pragma unroll
        for (int j = 0; j < GNN_NB; j++) {
            const int nd = g + j;
            if (nd < n_nodes) {
                const float nv = insT[tid * GNN_NB + j];   // node feature k=tid
                out[(size_t)nd * H_DIM + tid] = nv + o[j];
            }
        }
        __syncthreads();   // protect insT/hT reuse
    }
}

// ---------------- launch -----------------------------------------------------
extern "C" void kernel_launch(void* const* d_in, const int* in_sizes, int n_in,
                              void* d_out, int out_size)
{
    const float* lane_points   = (const float*)d_in[0];
    const float* agent_history = (const float*)d_in[1];
    const int* e_ll = (const int*)d_in[2];
    const int* e_aa = (const int*)d_in[3];
    const int* e_la = (const int*)d_in[4];
    const float* lw1 = (const float*)d_in[5];
    const float* lb1 = (const float*)d_in[6];
    const float* lw2 = (const float*)d_in[7];
    const float* lb2 = (const float*)d_in[8];
    const float* lw3 = (const float*)d_in[9];
    const float* lb3 = (const float*)d_in[10];
    const float* aw1 = (const float*)d_in[11];
    const float* ab1 = (const float*)d_in[12];
    const float* aw2 = (const float*)d_in[13];
    const float* ab2 = (const float*)d_in[14];
    const float* aw3 = (const float*)d_in[15];
    const float* ab3 = (const float*)d_in[16];
    const float* ll_w1 = (const float*)d_in[17];
    const float* ll_b1 = (const float*)d_in[18];
    const float* ll_w2 = (const float*)d_in[19];
    const float* ll_b2 = (const float*)d_in[20];
    const float* aa_w1 = (const float*)d_in[21];
    const float* aa_b1 = (const float*)d_in[22];
    const float* aa_w2 = (const float*)d_in[23];
    const float* aa_b2 = (const float*)d_in[24];
    const float* la_w1 = (const float*)d_in[25];
    const float* la_b1 = (const float*)d_in[26];
    const float* la_w2 = (const float*)d_in[27];
    const float* la_b2 = (const float*)d_in[28];

    float* out = (float*)d_out;
    float* lane_out  = out;
    float* agent_out = out + (size_t)N_LANE * H_DIM;

    float *p_lane_enc, *p_agent_enc, *p_lane_agg, *p_agent_agg, *p_deg_l, *p_deg_a;
    cudaGetSymbolAddress((void**)&p_lane_enc,  g_lane_enc);
    cudaGetSymbolAddress((void**)&p_agent_enc, g_agent_enc);
    cudaGetSymbolAddress((void**)&p_lane_agg,  g_lane_agg);
    cudaGetSymbolAddress((void**)&p_agent_agg, g_agent_agg);
    cudaGetSymbolAddress((void**)&p_deg_l,     g_deg_l);
    cudaGetSymbolAddress((void**)&p_deg_a,     g_deg_a);

    cudaFuncSetAttribute(encode_kernel, cudaFuncAttributeMaxDynamicSharedMemorySize, ENC_SMEM_BYTES);
    cudaFuncSetAttribute(gnn_kernel,    cudaFuncAttributeMaxDynamicSharedMemorySize, GNN_SMEM_BYTES);

    zero_all_kernel<<<2048, 256>>>();

    // encoders (256 threads, 2 node-slots; nodes_per_block even)
    encode_kernel<<<(N_LANE + 67) / 68, 256, ENC_SMEM_BYTES>>>(
        lane_points, lw1, lb1, lw2, lb2, lw3, lb3, p_lane_enc, N_LANE, 68);
    encode_kernel<<<(N_AGENT + 27) / 28, 256, ENC_SMEM_BYTES>>>(
        agent_history, aw1, ab1, aw2, ab2, aw3, ab3, p_agent_enc, N_AGENT, 28);

    // lane-lane GNN
    scatter_kernel<<<(E_LL + 7) / 8, 256>>>(e_ll, e_ll + E_LL, E_LL,
                                            p_lane_enc, p_lane_agg, p_deg_l);
    gnn_kernel<<<(N_LANE + 71) / 72, 128, GNN_SMEM_BYTES>>>(
        p_lane_enc, p_lane_agg, p_deg_l, ll_w1, ll_b1, ll_w2, ll_b2,
        lane_out, N_LANE, 72);

    // agent-agent GNN
    scatter_kernel<<<(E_AA + 7) / 8, 256>>>(e_aa, e_aa + E_AA, E_AA,
                                            p_agent_enc, p_agent_agg, p_deg_a);
    gnn_kernel<<<(N_AGENT + 31) / 32, 128, GNN_SMEM_BYTES>>>(
        p_agent_enc, p_agent_agg, p_deg_a, aa_w1, aa_b1, aa_w2, aa_b2,
        agent_out, N_AGENT, 32);

    // lane-agent GNN (source = updated lane, node = updated agent, in-place)
    zero_agent_kernel<<<1024, 256>>>();
    scatter_kernel<<<(E_LA + 7) / 8, 256>>>(e_la, e_la + E_LA, E_LA,
                                            lane_out, p_agent_agg, p_deg_a);
    gnn_kernel<<<(N_AGENT + 31) / 32, 128, GNN_SMEM_BYTES>>>(
        agent_out, p_agent_agg, p_deg_a, la_w1, la_b1, la_w2, la_b2,
        agent_out, N_AGENT, 32);
}

// round 4
// speedup vs baseline: 2.2867x; 1.6860x over previous
#include <cuda_runtime.h>
#include <cstddef>
#include <cstdint>

#define N_LANE  20000
#define P_LANE  20
#define N_AGENT 4000
#define T_AGENT 20
#define F_DIM   8
#define H_DIM   128
#define E_LL    640000
#define E_AA    128000
#define E_LA    200000

// ---------------- scratch (device globals; no allocation allowed) -----------
__device__ float g_lane_enc [N_LANE  * H_DIM];
__device__ float g_agent_enc[N_AGENT * H_DIM];
__device__ float g_lane_agg [N_LANE  * H_DIM];
__device__ float g_agent_agg[N_AGENT * H_DIM];
__device__ float g_ms      [N_LANE  * H_DIM];
__device__ float g_deg_l[N_LANE];
__device__ float g_deg_a[N_AGENT];

// ---------------- tf32 mma.sync helpers (sm_80+ PTX, works on plain sm_103) --
__device__ __forceinline__ uint32_t f2tf32(float f) {
    uint32_t u;
    asm("cvt.rna.tf32.f32 %0, %1;" : "=r"(u) : "f"(f));
    return u;
}
__device__ __forceinline__ void mma_tf32(float c[4], const uint32_t a[4],
                                         uint32_t b0, uint32_t b1) {
    asm("mma.sync.aligned.m16n8k8.row.col.f32.tf32.tf32.f32 "
        "{%0,%1,%2,%3}, {%4,%5,%6,%7}, {%8,%9}, {%0,%1,%2,%3};"
        : "+f"(c[0]), "+f"(c[1]), "+f"(c[2]), "+f"(c[3])
        : "r"(a[0]), "r"(a[1]), "r"(a[2]), "r"(a[3]), "r"(b0), "r"(b1));
}

// ---------------- packed f32x2 helpers (GNN path) ----------------------------
__device__ __forceinline__ void ffma2(unsigned long long& d,
                                      unsigned long long a,
                                      unsigned long long b) {
    asm("fma.rn.f32x2 %0, %1, %2, %0;" : "+l"(d) : "l"(a), "l"(b));
}
__device__ __forceinline__ unsigned long long pack_dup(float x) {
    unsigned long long r;
    unsigned u = __float_as_uint(x);
    asm("mov.b64 %0, {%1, %2};" : "=l"(r) : "r"(u), "r"(u));
    return r;
}
__device__ __forceinline__ float2 unpack2(unsigned long long v) {
    unsigned lo, hi;
    asm("mov.b64 {%0, %1}, %2;" : "=r"(lo), "=r"(hi) : "l"(v));
    return make_float2(__uint_as_float(lo), __uint_as_float(hi));
}

// ---------------- zero kernels ----------------------------------------------
__global__ void zero_all_kernel() {
    int i = blockIdx.x * blockDim.x + threadIdx.x;
    int stride = gridDim.x * blockDim.x;
    for (int k = i; k < N_LANE * H_DIM; k += stride) g_lane_agg[k] = 0.f;
    for (int k = i; k < N_AGENT * H_DIM; k += stride) g_agent_agg[k] = 0.f;
    for (int k = i; k < N_LANE; k += stride) g_deg_l[k] = 0.f;
    for (int k = i; k < N_AGENT; k += stride) g_deg_a[k] = 0.f;
}
__global__ void zero_agent_kernel() {
    int i = blockIdx.x * blockDim.x + threadIdx.x;
    int stride = gridDim.x * blockDim.x;
    for (int k = i; k < N_AGENT * H_DIM; k += stride) g_agent_agg[k] = 0.f;
    for (int k = i; k < N_AGENT; k += stride) g_deg_a[k] = 0.f;
}

// ---------------- tensor encoder (stages 1+2+max) ----------------------------
// Per tile: 6 nodes * 20 rows = 120 rows (pad to 128). D = relu-stage1 @ w2,
// then per-node max over 20 rows, + b2, relu -> g_ms.
// smem floats: A/D 128*132=16896 | B 128*136=17408 | xs 960 | w1s 1024 |
//              b1s 128 | b2s 128 | refv 16
#define ENC_TILE_NODES 6
#define SA 132
#define SB 136
#define ENC2_SMEM_FLOATS (16896 + 17408 + 960 + 1024 + 128 + 128 + 16)
#define ENC2_SMEM_BYTES  (ENC2_SMEM_FLOATS * 4)

__global__ void __launch_bounds__(256, 1)
enc_mma_kernel(const float* __restrict__ x_in,
               const float* __restrict__ w1, const float* __restrict__ b1,
               const float* __restrict__ w2, const float* __restrict__ b2,
               float* __restrict__ ms_out, int n_nodes, int n_tiles)
{
    extern __shared__ float smem[];
    float* A    = smem;               // tf32 bits during mma, f32 Dbuf after
    float* B    = A + 16896;          // tf32 bits of w2 [k][n], stride SB
    float* xs   = B + 17408;
    float* w1s  = xs + 960;
    float* b1s  = w1s + 1024;
    float* b2s  = b1s + 128;
    float* refv = b2s + 128;

    uint32_t* Au = (uint32_t*)A;
    uint32_t* Bu = (uint32_t*)B;

    const int tid = threadIdx.x;
    const int wid = tid >> 5;
    const int lane = tid & 31;
    const int tg = lane >> 2;          // group id (0..7)
    const int tq = lane & 3;           // thread in group (0..3)
    const int warp_m = wid & 3;        // row group: 32 rows
    const int warp_n = wid >> 2;       // col group: 64 cols

    // static: B[k][n] = tf32(w2[k*128+n]); w1, biases plain f32
    for (int i = tid; i < H_DIM * H_DIM; i += 256) {
        int k = i >> 7, n = i & 127;
        Bu[k * SB + n] = f2tf32(w2[i]);
    }
    for (int i = tid; i < F_DIM * H_DIM; i += 256) w1s[i] = w1[i];
    if (tid < H_DIM) { b1s[tid] = b1[tid]; b2s[tid] = b2[tid]; }
    __syncthreads();

    const int c  = tid & 127;
    const int rh = tid >> 7;
    float wa[F_DIM];
#pragma unroll
    for (int f = 0; f < F_DIM; f++) wa[f] = w1s[f * H_DIM + c];
    const float b1v = b1s[c];

    for (int tile = blockIdx.x; tile < n_tiles; tile += gridDim.x) {
        const int node0 = tile * ENC_TILE_NODES;

        // ---- load x (6 nodes x 160), clamped ----
        for (int i = tid; i < ENC_TILE_NODES * P_LANE * F_DIM; i += 256) {
            int j = i / (P_LANE * F_DIM);
            int nd = node0 + j; if (nd >= n_nodes) nd = n_nodes - 1;
            xs[i] = x_in[(size_t)nd * (P_LANE * F_DIM) + (i - j * (P_LANE * F_DIM))];
        }
        __syncthreads();
        if (tid < 2 * ENC_TILE_NODES)
            refv[tid] = xs[(tid >> 1) * 160 + 19 * 8 + (tid & 1)];
        __syncthreads();
        if (tid < 240) {
            int j = tid / 40, rem = tid % 40, t = rem >> 1, f = rem & 1;
            xs[j * 160 + t * 8 + f] -= refv[j * 2 + f];
        }
        __syncthreads();

        // ---- stage 1: A(r,c) = tf32(relu(b1 + x'[r].w1[:,c])), r<120 ----
        for (int i = 0; i < 60; i++) {
            const int r = rh * 60 + i;
            const float4* xp = (const float4*)(xs + r * 8);
            const float4 x0 = xp[0], x1 = xp[1];
            float s = b1v;
            s = fmaf(x0.x, wa[0], s); s = fmaf(x0.y, wa[1], s);
            s = fmaf(x0.z, wa[2], s); s = fmaf(x0.w, wa[3], s);
            s = fmaf(x1.x, wa[4], s); s = fmaf(x1.y, wa[5], s);
            s = fmaf(x1.z, wa[6], s); s = fmaf(x1.w, wa[7], s);
            Au[r * SA + c] = f2tf32(fmaxf(s, 0.f));
        }
        // zero pad rows 120..127 (avoid stale Dbuf junk feeding inf/nan paths)
        if (tid < 128) Au[(120 + (tid >> 4)) * SA + ((tid & 15) + rh * 0)] = 0;  // partial; harmless
        __syncthreads();

        // ---- mma: D[128x128] = A @ B, warp tile 32x64 ----
        float cfr[2][8][4];
#pragma unroll
        for (int mt = 0; mt < 2; mt++)
#pragma unroll
            for (int nt = 0; nt < 8; nt++)
#pragma unroll
                for (int q = 0; q < 4; q++) cfr[mt][nt][q] = 0.f;

#pragma unroll 2
        for (int kc = 0; kc < 16; kc++) {
            const int k0 = kc * 8;
            uint32_t afr[2][4];
#pragma unroll
            for (int mt = 0; mt < 2; mt++) {
                const int rm = warp_m * 32 + mt * 16;
                afr[mt][0] = Au[(rm + tg) * SA + k0 + tq];
                afr[mt][1] = Au[(rm + tg + 8) * SA + k0 + tq];
                afr[mt][2] = Au[(rm + tg) * SA + k0 + tq + 4];
                afr[mt][3] = Au[(rm + tg + 8) * SA + k0 + tq + 4];
            }
#pragma unroll
            for (int nt = 0; nt < 8; nt++) {
                const int n0 = warp_n * 64 + nt * 8;
                const uint32_t b0 = Bu[(k0 + tq) * SB + n0 + tg];
                const uint32_t b1f = Bu[(k0 + tq + 4) * SB + n0 + tg];
                mma_tf32(cfr[0][nt], afr[0], b0, b1f);
                mma_tf32(cfr[1][nt], afr[1], b0, b1f);
            }
        }
        __syncthreads();   // all A reads done; A memory becomes Dbuf

        // ---- store C frags to Dbuf (stride SA) ----
#pragma unroll
        for (int mt = 0; mt < 2; mt++) {
            const int rr = warp_m * 32 + mt * 16 + tg;
#pragma unroll
            for (int nt = 0; nt < 8; nt++) {
                const int cc = warp_n * 64 + nt * 8 + 2 * tq;
                *(float2*)(A + rr * SA + cc) =
                    make_float2(cfr[mt][nt][0], cfr[mt][nt][1]);
                *(float2*)(A + (rr + 8) * SA + cc) =
                    make_float2(cfr[mt][nt][2], cfr[mt][nt][3]);
            }
        }
        __syncthreads();

        // ---- per-node max over 20 rows + bias + relu -> g_ms ----
        for (int task = tid; task < ENC_TILE_NODES * H_DIM; task += 256) {
            const int j = task >> 7, cc = task & 127;
            const int nd = node0 + j;
            if (nd < n_nodes) {
                float m = -3.4e38f;
                const float* dp = A + (j * 20) * SA + cc;
#pragma unroll
                for (int r = 0; r < 20; r++) m = fmaxf(m, dp[r * SA]);
                ms_out[(size_t)nd * H_DIM + cc] = fmaxf(m + b2s[cc], 0.f);
            }
        }
        __syncthreads();
    }
}

// ---------------- tensor MLP: out = relu(in @ w + b), 128-row tiles ----------
#define MLP_SMEM_FLOATS (16896 + 17408 + 128)
#define MLP_SMEM_BYTES  (MLP_SMEM_FLOATS * 4)

__global__ void __launch_bounds__(256, 1)
mlp_mma_kernel(const float* __restrict__ in_feat,
               const float* __restrict__ w, const float* __restrict__ b,
               float* __restrict__ out, int n_nodes)
{
    extern __shared__ float smem[];
    float* A  = smem;
    float* B  = A + 16896;
    float* bs = B + 17408;
    uint32_t* Au = (uint32_t*)A;
    uint32_t* Bu = (uint32_t*)B;

    const int tid = threadIdx.x;
    const int wid = tid >> 5;
    const int lane = tid & 31;
    const int tg = lane >> 2;
    const int tq = lane & 3;
    const int warp_m = wid & 3;
    const int warp_n = wid >> 2;

    for (int i = tid; i < H_DIM * H_DIM; i += 256) {
        int k = i >> 7, n = i & 127;
        Bu[k * SB + n] = f2tf32(w[i]);
    }
    if (tid < H_DIM) bs[tid] = b[tid];

    const int n0 = blockIdx.x * 128;
    {
        const int c  = tid & 127;
        const int r0 = (tid >> 7) * 64;
        for (int i = 0; i < 64; i++) {
            int r = r0 + i;
            int idx = n0 + r; if (idx >= n_nodes) idx = n_nodes - 1;
            Au[r * SA + c] = f2tf32(in_feat[(size_t)idx * H_DIM + c]);
        }
    }
    __syncthreads();

    float cfr[2][8][4];
#pragma unroll
    for (int mt = 0; mt < 2; mt++)
#pragma unroll
        for (int nt = 0; nt < 8; nt++)
#pragma unroll
            for (int q = 0; q < 4; q++) cfr[mt][nt][q] = 0.f;

#pragma unroll 2
    for (int kc = 0; kc < 16; kc++) {
        const int k0 = kc * 8;
        uint32_t afr[2][4];
#pragma unroll
        for (int mt = 0; mt < 2; mt++) {
            const int rm = warp_m * 32 + mt * 16;
            afr[mt][0] = Au[(rm + tg) * SA + k0 + tq];
            afr[mt][1] = Au[(rm + tg + 8) * SA + k0 + tq];
            afr[mt][2] = Au[(rm + tg) * SA + k0 + tq + 4];
            afr[mt][3] = Au[(rm + tg + 8) * SA + k0 + tq + 4];
        }
#pragma unroll
        for (int nt = 0; nt < 8; nt++) {
            const int nn = warp_n * 64 + nt * 8;
            const uint32_t b0 = Bu[(k0 + tq) * SB + nn + tg];
            const uint32_t b1f = Bu[(k0 + tq + 4) * SB + nn + tg];
            mma_tf32(cfr[0][nt], afr[0], b0, b1f);
            mma_tf32(cfr[1][nt], afr[1], b0, b1f);
        }
    }

    // epilogue: bias + relu + direct STG
    float2 bv[8];
#pragma unroll
    for (int nt = 0; nt < 8; nt++) {
        const int cc = warp_n * 64 + nt * 8 + 2 * tq;
        bv[nt] = make_float2(bs[cc], bs[cc + 1]);
    }
#pragma unroll
    for (int mt = 0; mt < 2; mt++) {
        const int rr = warp_m * 32 + mt * 16 + tg;
#pragma unroll
        for (int half = 0; half < 2; half++) {
            const int nd = n0 + rr + half * 8;
            if (nd < n_nodes) {
#pragma unroll
                for (int nt = 0; nt < 8; nt++) {
                    const int cc = warp_n * 64 + nt * 8 + 2 * tq;
                    const float v0 = cfr[mt][nt][half * 2 + 0] + bv[nt].x;
                    const float v1 = cfr[mt][nt][half * 2 + 1] + bv[nt].y;
                    *(float2*)(out + (size_t)nd * H_DIM + cc) =
                        make_float2(fmaxf(v0, 0.f), fmaxf(v1, 0.f));
                }
            }
        }
    }
}

// ---------------- edge scatter (segment_sum via vector RED) -----------------
__global__ void scatter_kernel(const int* __restrict__ src_idx,
                               const int* __restrict__ dst_idx, int n_edges,
                               const float* __restrict__ feat,
                               float* __restrict__ agg, float* __restrict__ deg)
{
    const int warp = (blockIdx.x * blockDim.x + threadIdx.x) >> 5;
    const int lane = threadIdx.x & 31;
    if (warp >= n_edges) return;
    const int s = src_idx[warp];
    const int d = dst_idx[warp];
    const float4 v = ((const float4*)(feat + (size_t)s * H_DIM))[lane];
    float4* a = ((float4*)(agg + (size_t)d * H_DIM)) + lane;
    asm volatile("red.global.add.v4.f32 [%0], {%1,%2,%3,%4};"
                 :: "l"(a), "f"(v.x), "f"(v.y), "f"(v.z), "f"(v.w) : "memory");
    if (lane == 0) atomicAdd(deg + d, 1.0f);
}

// ---------------- edge GNN node MLP: 8-node register-blocked GEMM -----------
#define GNN_NB 8
#define GNN_SMEM_FLOATS (2*H_DIM*H_DIM + H_DIM*H_DIM + 2*H_DIM + 2*H_DIM*GNN_NB + H_DIM*GNN_NB)
#define GNN_SMEM_BYTES  (GNN_SMEM_FLOATS * 4)

__global__ void __launch_bounds__(128, 1)
gnn_kernel(const float* __restrict__ node_in,
           const float* __restrict__ agg, const float* __restrict__ deg,
           const float* __restrict__ w1, const float* __restrict__ b1,
           const float* __restrict__ w2, const float* __restrict__ b2,
           float* __restrict__ out, int n_nodes, int nodes_per_block)
{
    extern __shared__ float smem[];
    float* w1s  = smem;
    float* w2s  = w1s + 2 * H_DIM * H_DIM;
    float* b1s  = w2s + H_DIM * H_DIM;
    float* b2s  = b1s + H_DIM;
    float* insT = b2s + H_DIM;
    float* hT   = insT + 2 * H_DIM * GNN_NB;

    const int tid = threadIdx.x;
    for (int i = tid; i < 2 * H_DIM * H_DIM; i += 128) w1s[i] = w1[i];
    for (int i = tid; i < H_DIM * H_DIM; i += 128) w2s[i] = w2[i];
    if (tid < H_DIM) { b1s[tid] = b1[tid]; b2s[tid] = b2[tid]; }
    __syncthreads();

    const float b1v = b1s[tid];
    const float b2v = b2s[tid];

    const int node0 = blockIdx.x * nodes_per_block;
    int node1 = node0 + nodes_per_block;
    if (node1 > n_nodes) node1 = n_nodes;

    const int jld = tid >> 4;
    const int lld = tid & 15;

    for (int g = node0; g < node1; g += GNN_NB) {
        {
            int nd = g + jld;
            if (nd >= n_nodes) nd = n_nodes - 1;
            const float invd = 1.0f / fmaxf(deg[nd], 1.0f);
            const float* np = node_in + (size_t)nd * H_DIM;
            const float* ap = agg + (size_t)nd * H_DIM;
#pragma unroll
            for (int r = 0; r < 8; r++) {
                const int k = lld + 16 * r;
                insT[k * GNN_NB + jld] = np[k];
                insT[(H_DIM + k) * GNN_NB + jld] = ap[k] * invd;
            }
        }
        __syncthreads();

        unsigned long long acc[4];
        {
            const unsigned long long bp = pack_dup(b1v);
#pragma unroll
            for (int j = 0; j < 4; j++) acc[j] = bp;
        }
#pragma unroll 4
        for (int k = 0; k < 2 * H_DIM; k++) {
            const unsigned long long wp = pack_dup(w1s[k * H_DIM + tid]);
            const ulonglong2* ip = ((const ulonglong2*)insT) + k * 2;
            const ulonglong2 a = ip[0];
            const ulonglong2 b = ip[1];
            ffma2(acc[0], a.x, wp);
            ffma2(acc[1], a.y, wp);
            ffma2(acc[2], b.x, wp);
            ffma2(acc[3], b.y, wp);
        }
        {
            const float2 v0 = unpack2(acc[0]);
            const float2 v1 = unpack2(acc[1]);
            const float2 v2 = unpack2(acc[2]);
            const float2 v3 = unpack2(acc[3]);
            float4* hp = (float4*)(hT + tid * GNN_NB);
            hp[0] = make_float4(fmaxf(v0.x, 0.f), fmaxf(v0.y, 0.f),
                                fmaxf(v1.x, 0.f), fmaxf(v1.y, 0.f));
            hp[1] = make_float4(fmaxf(v2.x, 0.f), fmaxf(v2.y, 0.f),
                                fmaxf(v3.x, 0.f), fmaxf(v3.y, 0.f));
        }
        __syncthreads();

        {
            const unsigned long long bp = pack_dup(b2v);
#pragma unroll
            for (int j = 0; j < 4; j++) acc[j] = bp;
        }
#pragma unroll 4
        for (int k = 0; k < H_DIM; k++) {
            const unsigned long long wp = pack_dup(w2s[k * H_DIM + tid]);
            const ulonglong2* hp = ((const ulonglong2*)hT) + k * 2;
            const ulonglong2 a = hp[0];
            const ulonglong2 b = hp[1];
            ffma2(acc[0], a.x, wp);
            ffma2(acc[1], a.y, wp);
            ffma2(acc[2], b.x, wp);
            ffma2(acc[3], b.y, wp);
        }

        float o[GNN_NB];
        {
            const float2 v0 = unpack2(acc[0]);
            const float2 v1 = unpack2(acc[1]);
            const float2 v2 = unpack2(acc[2]);
            const float2 v3 = unpack2(acc[3]);
            o[0] = fmaxf(v0.x, 0.f); o[1] = fmaxf(v0.y, 0.f);
            o[2] = fmaxf(v1.x, 0.f); o[3] = fmaxf(v1.y, 0.f);
            o[4] = fmaxf(v2.x, 0.f); o[5] = fmaxf(v2.y, 0.f);
            o[6] = fmaxf(v3.x, 0.f); o[7] = fmaxf(v3.y, 0.f);
        }
#pragma unroll
        for (int j = 0; j < GNN_NB; j++) {
            const int nd = g + j;
            if (nd < n_nodes) {
                const float nv = insT[tid * GNN_NB + j];
                out[(size_t)nd * H_DIM + tid] = nv + o[j];
            }
        }
        __syncthreads();
    }
}

// ---------------- launch -----------------------------------------------------
extern "C" void kernel_launch(void* const* d_in, const int* in_sizes, int n_in,
                              void* d_out, int out_size)
{
    const float* lane_points   = (const float*)d_in[0];
    const float* agent_history = (const float*)d_in[1];
    const int* e_ll = (const int*)d_in[2];
    const int* e_aa = (const int*)d_in[3];
    const int* e_la = (const int*)d_in[4];
    const float* lw1 = (const float*)d_in[5];
    const float* lb1 = (const float*)d_in[6];
    const float* lw2 = (const float*)d_in[7];
    const float* lb2 = (const float*)d_in[8];
    const float* lw3 = (const float*)d_in[9];
    const float* lb3 = (const float*)d_in[10];
    const float* aw1 = (const float*)d_in[11];
    const float* ab1 = (const float*)d_in[12];
    const float* aw2 = (const float*)d_in[13];
    const float* ab2 = (const float*)d_in[14];
    const float* aw3 = (const float*)d_in[15];
    const float* ab3 = (const float*)d_in[16];
    const float* ll_w1 = (const float*)d_in[17];
    const float* ll_b1 = (const float*)d_in[18];
    const float* ll_w2 = (const float*)d_in[19];
    const float* ll_b2 = (const float*)d_in[20];
    const float* aa_w1 = (const float*)d_in[21];
    const float* aa_b1 = (const float*)d_in[22];
    const float* aa_w2 = (const float*)d_in[23];
    const float* aa_b2 = (const float*)d_in[24];
    const float* la_w1 = (const float*)d_in[25];
    const float* la_b1 = (const float*)d_in[26];
    const float* la_w2 = (const float*)d_in[27];
    const float* la_b2 = (const float*)d_in[28];

    float* out = (float*)d_out;
    float* lane_out  = out;
    float* agent_out = out + (size_t)N_LANE * H_DIM;

    float *p_lane_enc, *p_agent_enc, *p_lane_agg, *p_agent_agg, *p_ms, *p_deg_l, *p_deg_a;
    cudaGetSymbolAddress((void**)&p_lane_enc,  g_lane_enc);
    cudaGetSymbolAddress((void**)&p_agent_enc, g_agent_enc);
    cudaGetSymbolAddress((void**)&p_lane_agg,  g_lane_agg);
    cudaGetSymbolAddress((void**)&p_agent_agg, g_agent_agg);
    cudaGetSymbolAddress((void**)&p_ms,        g_ms);
    cudaGetSymbolAddress((void**)&p_deg_l,     g_deg_l);
    cudaGetSymbolAddress((void**)&p_deg_a,     g_deg_a);

    cudaFuncSetAttribute(enc_mma_kernel, cudaFuncAttributeMaxDynamicSharedMemorySize, ENC2_SMEM_BYTES);
    cudaFuncSetAttribute(mlp_mma_kernel, cudaFuncAttributeMaxDynamicSharedMemorySize, MLP_SMEM_BYTES);
    cudaFuncSetAttribute(gnn_kernel,     cudaFuncAttributeMaxDynamicSharedMemorySize, GNN_SMEM_BYTES);

    const int agent_tiles = (N_AGENT + ENC_TILE_NODES - 1) / ENC_TILE_NODES;
    const int lane_tiles  = (N_LANE + ENC_TILE_NODES - 1) / ENC_TILE_NODES;

    zero_all_kernel<<<2048, 256>>>();
    enc_mma_kernel<<<148, 256, ENC2_SMEM_BYTES>>>(
        agent_history, aw1, ab1, aw2, ab2, p_ms, N_AGENT, agent_tiles);
    mlp_mma_kernel<<<(N_AGENT + 127) / 128, 256, MLP_SMEM_BYTES>>>(
        p_ms, aw3, ab3, p_agent_enc, N_AGENT);
    enc_mma_kernel<<<148, 256, ENC2_SMEM_BYTES>>>(
        lane_points, lw1, lb1, lw2, lb2, p_ms, N_LANE, lane_tiles);
    mlp_mma_kernel<<<(N_LANE + 127) / 128, 256, MLP_SMEM_BYTES>>>(
        p_ms, lw3, lb3, p_lane_enc, N_LANE);

    scatter_kernel<<<(E_LL + 7) / 8, 256>>>(e_ll, e_ll + E_LL, E_LL,
                                            p_lane_enc, p_lane_agg, p_deg_l);
    gnn_kernel<<<(N_LANE + 71) / 72, 128, GNN_SMEM_BYTES>>>(
        p_lane_enc, p_lane_agg, p_deg_l, ll_w1, ll_b1, ll_w2, ll_b2,
        lane_out, N_LANE, 72);

    scatter_kernel<<<(E_AA + 7) / 8, 256>>>(e_aa, e_aa + E_AA, E_AA,
                                            p_agent_enc, p_agent_agg, p_deg_a);
    gnn_kernel<<<(N_AGENT + 31) / 32, 128, GNN_SMEM_BYTES>>>(
        p_agent_enc, p_agent_agg, p_deg_a, aa_w1, aa_b1, aa_w2, aa_b2,
        agent_out, N_AGENT, 32);

    zero_agent_kernel<<<1024, 256>>>();
    scatter_kernel<<<(E_LA + 7) / 8, 256>>>(e_la, e_la + E_LA, E_LA,
                                            lane_out, p_agent_agg, p_deg_a);
    gnn_kernel<<<(N_AGENT + 31) / 32, 128, GNN_SMEM_BYTES>>>(
        agent_out, p_agent_agg, p_deg_a, la_w1, la_b1, la_w2, la_b2,
        agent_out, N_AGENT, 32);
}